// round 14
// baseline (speedup 1.0000x reference)
#include <cuda_runtime.h>
#include <math.h>

#define SLEN 1024
#define NM   32
#define HID  128
#define NB   1024

typedef unsigned long long u64;

// ---------------- scratch (static device memory; no allocation) ----------------
__device__ float g_tabC[SLEN*NM];          // cos(2*pi*m*s/S), [s][m]
__device__ float g_tabS[SLEN*NM];          // sin(2*pi*m*s/S), [s][m]
__device__ float g_w1tr[NM*HID];           // [m][ch]
__device__ float g_w1ti[NM*HID];
__device__ u64   g_w2p[NM*HID*HID];        // [m][i][o] packed (wr, wi)
__device__ u64   g_w2n[NM*HID*HID];        // [m][i][o] packed (-wi, wr)
__device__ float g_Zf [2*NM*NB*HID];       // [(m*2+ri)][b][ch]
__device__ float g_of2[2*NM*NB*HID];       // [(m*2+ri)][b][o]

// ---------------- packed f32x2 helpers ----------------
__device__ __forceinline__ u64 pk2(float lo, float hi) {
    u64 r; asm("mov.b64 %0, {%1, %2};" : "=l"(r) : "f"(lo), "f"(hi)); return r;
}
__device__ __forceinline__ void un2(u64 v, float& lo, float& hi) {
    asm("mov.b64 {%0, %1}, %2;" : "=f"(lo), "=f"(hi) : "l"(v));
}
__device__ __forceinline__ u64 f2fma(u64 a, u64 b, u64 c) {
    u64 d; asm("fma.rn.f32x2 %0, %1, %2, %3;" : "=l"(d) : "l"(a), "l"(b), "l"(c)); return d;
}
__device__ __forceinline__ u64 f2mul(u64 a, u64 b) {
    u64 d; asm("mul.rn.f32x2 %0, %1, %2;" : "=l"(d) : "l"(a), "l"(b)); return d;
}
__device__ __forceinline__ u64 f2add(u64 a, u64 b) {
    u64 d; asm("add.rn.f32x2 %0, %1, %2;" : "=l"(d) : "l"(a), "l"(b)); return d;
}
__device__ __forceinline__ unsigned s2u(const void* p) {
    return (unsigned)__cvta_generic_to_shared(p);
}
// 16B shared load -> two packed f32x2 operands
__device__ __forceinline__ void lds2u64(u64& a, u64& b, unsigned addr) {
    asm volatile("ld.shared.v2.u64 {%0, %1}, [%2];" : "=l"(a), "=l"(b) : "r"(addr));
}
#define PKC(x) pk2((x), (x))

// High-accuracy GELU (A&S 7.1.26 erf), used on special points only.
__device__ __forceinline__ float gelu_fast(float x) {
    float q    = fabsf(x) * 0.70710678118654752f;
    float t    = __fdividef(1.0f, fmaf(0.3275911f, q, 1.0f));
    float poly = fmaf(fmaf(fmaf(fmaf(1.061405429f, t, -1.453152027f),
                               t, 1.421413741f),
                          t, -0.284496736f),
                      t, 0.254829592f) * t;
    float er   = 1.0f - poly * __expf(-q * q);
    float phi  = fmaf(copysignf(er, x), 0.5f, 0.5f);
    return x * phi;
}

// Two-point GELU, hot path: A&S 7.1.25 3-term erf (abs err 2.5e-5), packed poly.
__device__ __forceinline__ void gelu2(float xa, float xb, float& za, float& zb) {
    float qa = fabsf(xa) * 0.70710678118654752f;
    float qb = fabsf(xb) * 0.70710678118654752f;
    float ta = __fdividef(1.0f, fmaf(0.47047f, qa, 1.0f));
    float tb = __fdividef(1.0f, fmaf(0.47047f, qb, 1.0f));
    u64 t2 = pk2(ta, tb);
    u64 p  = f2fma(t2, PKC(0.7478556f), PKC(-0.0958798f));
    p = f2fma(p, t2, PKC(0.3480242f));
    p = f2mul(p, t2);
    float ea = __expf(-qa * qa), eb = __expf(-qb * qb);
    float pa, pb; un2(p, pa, pb);
    float era = fmaf(-pa, ea, 1.0f), erb = fmaf(-pb, eb, 1.0f);
    za = xa * fmaf(copysignf(era, xa), 0.5f, 0.5f);
    zb = xb * fmaf(copysignf(erb, xb), 0.5f, 0.5f);
}

// ---------------- K_tab: exact trig tables ----------------
__global__ void k_tab() {
    int idx = blockIdx.x * blockDim.x + threadIdx.x;
    if (idx >= SLEN * NM) return;
    int s = idx >> 5, m = idx & 31;
    int k = (s * m) & (SLEN - 1);
    float x = (float)k * (1.0f / 512.0f);
    float sv, cv;
    sincospif(x, &sv, &cv);
    g_tabC[idx] = cv;
    g_tabS[idx] = sv;
}

// ---------------- K_w: weight transposes + complex packing ----------------
__global__ void k_w(const float* __restrict__ w1r, const float* __restrict__ w1i,
                    const float* __restrict__ w2r, const float* __restrict__ w2i) {
    int tid = blockIdx.x * blockDim.x + threadIdx.x;
    if (tid < NM * HID) {
        int ch = tid >> 5, m = tid & 31;
        g_w1tr[m * HID + ch] = w1r[tid];
        g_w1ti[m * HID + ch] = w1i[tid];
    }
    if (tid < NM * HID * HID) {
        int m = tid & 31; int io = tid >> 5;
        int i = io >> 7;  int o = io & 127;
        float wr = w2r[tid], wi = w2i[tid];
        size_t dst = ((size_t)m * HID + i) * HID + o;
        g_w2p[dst] = pk2(wr, wi);
        g_w2n[dst] = pk2(-wi, wr);
    }
}

// ---------------- K_layer1: DFT(h) -> mix w1 -> synth+gelu+analyze (smem tables) -------
__global__ __launch_bounds__(256, 2) void k_layer1(const float* __restrict__ hin) {
    __shared__ float h_sm[SLEN];
    __shared__ float red[64 * 4];
    __shared__ float Hf[64];                   // [0:32) real, [32:64) imag
    __shared__ __align__(16) float smC[64 * 32];   // 64-row chunk of cos table
    __shared__ __align__(16) float smS[64 * 32];   // 64-row chunk of sin table
    int b = blockIdx.x;
    int t = threadIdx.x;

    // stage h row
    {
        const float4* src = reinterpret_cast<const float4*>(hin + (size_t)b * SLEN);
        float4* dst = reinterpret_cast<float4*>(h_sm);
        for (int j = t; j < SLEN / 4; j += 256) dst[j] = src[j];
    }
    __syncthreads();

    // forward DFT of h: Hfr[m] = sum h*cos, Hfi[m] = -sum h*sin
    {
        int out = t & 63, seg = t >> 6;
        int m = out & 31; int isI = out >> 5;
        const float* tab = isI ? g_tabS : g_tabC;
        float acc = 0.0f;
        int s0 = seg * 256;
        #pragma unroll 8
        for (int j = 0; j < 256; j++) {
            int s = s0 + j;
            acc = fmaf(h_sm[s], __ldg(&tab[s * NM + m]), acc);
        }
        red[out * 4 + seg] = acc;
    }
    __syncthreads();
    if (t < 64) {
        float v = red[t * 4] + red[t * 4 + 1] + red[t * 4 + 2] + red[t * 4 + 3];
        Hf[t] = (t >= 32) ? -v : v;
    }
    __syncthreads();

    int lane = t & 31;
    int w    = t >> 5;
    int hh   = lane >> 4;                      // mode-half / point-group owner
    int ch   = w * 16 + (lane & 15);
    float sgn  = hh ? -1.0f : 1.0f;
    float msgn = -sgn;

    // synthesis coefficients: y(s) = sum ar[m]*cos + ai[m]*sin
    float ar[16], ai[16], zfr[16], zfi[16];
    #pragma unroll
    for (int j = 0; j < 16; j++) {
        int m = hh * 16 + j;
        float hr = Hf[m], hi = Hf[32 + m];
        float a1 = __ldg(&g_w1tr[m * HID + ch]);
        float b1 = __ldg(&g_w1ti[m * HID + ch]);
        float km = (m == 0) ? (1.0f / SLEN) : (2.0f / SLEN);
        ar[j] = km * (hr * a1 - hi * b1);
        float oi = km * (hr * b1 + hi * a1);
        ai[j] = (m == 0) ? 0.0f : -oi;         // DC imag dropped by irfft
        zfr[j] = 0.0f; zfi[j] = 0.0f;
    }

    const float4* tC = reinterpret_cast<const float4*>(g_tabC);
    const float4* tS = reinterpret_cast<const float4*>(g_tabS);
    int base = hh * 4;                         // float4 offset inside 8-float4 row

    // special points s=0 and s=512 (sin == 0 there)
    {
        float c0[16], c5[16];
        #pragma unroll
        for (int q = 0; q < 4; q++) {
            float4 a = __ldg(&tC[0 * 8 + base + q]);
            float4 c = __ldg(&tC[512 * 8 + base + q]);
            c0[4*q+0]=a.x; c0[4*q+1]=a.y; c0[4*q+2]=a.z; c0[4*q+3]=a.w;
            c5[4*q+0]=c.x; c5[4*q+1]=c.y; c5[4*q+2]=c.z; c5[4*q+3]=c.w;
        }
        float u0 = 0.0f, u5 = 0.0f;
        #pragma unroll
        for (int j = 0; j < 16; j++) {
            u0 = fmaf(ar[j], c0[j], u0);
            u5 = fmaf(ar[j], c5[j], u5);
        }
        u0 += __shfl_xor_sync(0xffffffffu, u0, 16);
        u5 += __shfl_xor_sync(0xffffffffu, u5, 16);
        float z0 = gelu_fast(u0), z5 = gelu_fast(u5);
        #pragma unroll
        for (int j = 0; j < 16; j++)
            zfr[j] = fmaf(z0, c0[j], fmaf(z5, c5[j], zfr[j]));
    }

    // special pair s=256 / s=768 (half-wave symmetry)
    {
        float c[16], sn[16];
        #pragma unroll
        for (int q = 0; q < 4; q++) {
            float4 a = __ldg(&tC[256 * 8 + base + q]);
            float4 s = __ldg(&tS[256 * 8 + base + q]);
            c [4*q+0]=a.x; c [4*q+1]=a.y; c [4*q+2]=a.z; c [4*q+3]=a.w;
            sn[4*q+0]=s.x; sn[4*q+1]=s.y; sn[4*q+2]=s.z; sn[4*q+3]=s.w;
        }
        float u = 0.0f, v = 0.0f;
        #pragma unroll
        for (int j = 0; j < 16; j++) {
            u = fmaf(ar[j], c[j], u);
            v = fmaf(ai[j], sn[j], v);
        }
        float ya = u + v, yb = u - v;          // y(256), y(768)
        ya += __shfl_xor_sync(0xffffffffu, ya, 16);
        yb += __shfl_xor_sync(0xffffffffu, yb, 16);
        float ymine = hh ? yb : ya;
        float zmine = gelu_fast(ymine);
        float zoth  = __shfl_xor_sync(0xffffffffu, zmine, 16);
        float z0 = hh ? zoth : zmine;          // z(256)
        float z1 = hh ? zmine : zoth;          // z(768)
        float zp = z0 + z1, zd = z1 - z0;
        #pragma unroll
        for (int j = 0; j < 16; j++) {
            zfr[j] = fmaf(zp, c[j],  zfr[j]);
            zfi[j] = fmaf(zd, sn[j], zfi[j]);
        }
    }

    // pack coefficients and accumulators into f32x2 pairs (even/odd mode lanes)
    u64 ar2[8], ai2[8], zfr2[8], zfi2[8];
    #pragma unroll
    for (int k = 0; k < 8; k++) {
        ar2[k]  = pk2(ar[2*k],  ar[2*k+1]);
        ai2[k]  = pk2(ai[2*k],  ai[2*k+1]);
        zfr2[k] = pk2(zfr[2*k], zfr[2*k+1]);
        zfi2[k] = pk2(zfi[2*k], zfi[2*k+1]);
    }

    unsigned smC_a = s2u(smC) + hh * 64;       // hh selects 16-float half of row
    unsigned smS_a = s2u(smS) + hh * 64;

    // quad points {p, 1024-p, 512+p, 512-p}, p = 1..255, smem-staged tables
    for (int pb = 0; pb < 256; pb += 64) {
        __syncthreads();
        // cooperative stage: rows pb..pb+63 of both tables (512 float4 each)
        for (int j = t; j < 512; j += 256) {
            int row = j >> 3, col = j & 7;
            reinterpret_cast<float4*>(smC)[j] = __ldg(&tC[(pb + row) * 8 + col]);
            reinterpret_cast<float4*>(smS)[j] = __ldg(&tS[(pb + row) * 8 + col]);
        }
        __syncthreads();
        int p0 = (pb == 0) ? 1 : pb;
        for (int p = p0; p < pb + 64; p++) {
            unsigned off = (unsigned)(p - pb) * 128;   // 32 floats/row
            u64 c2[8], s2[8];
            lds2u64(c2[0], c2[1], smC_a + off);
            lds2u64(c2[2], c2[3], smC_a + off + 16);
            lds2u64(c2[4], c2[5], smC_a + off + 32);
            lds2u64(c2[6], c2[7], smC_a + off + 48);
            lds2u64(s2[0], s2[1], smS_a + off);
            lds2u64(s2[2], s2[3], smS_a + off + 16);
            lds2u64(s2[4], s2[5], smS_a + off + 32);
            lds2u64(s2[6], s2[7], smS_a + off + 48);

            // split accumulation chains (2x4 deep) for latency
            u64 u2a = 0ull, u2b = 0ull, v2a = 0ull, v2b = 0ull;
            #pragma unroll
            for (int k = 0; k < 4; k++) {
                u2a = f2fma(ar2[k],     c2[k],     u2a);
                u2b = f2fma(ar2[k + 4], c2[k + 4], u2b);
                v2a = f2fma(ai2[k],     s2[k],     v2a);
                v2b = f2fma(ai2[k + 4], s2[k + 4], v2b);
            }
            float ue, uo, ve, vo;
            un2(f2add(u2a, u2b), ue, uo);
            un2(f2add(v2a, v2b), ve, vo);
            // select-free parity folds: keep = my points' combo, send = partner's
            float keepU = fmaf(sgn,  uo, ue);
            float sendU = fmaf(msgn, uo, ue);
            float keepV = fmaf(sgn,  vo, ve);
            float sendV = fmaf(msgn, vo, ve);
            float U = keepU + __shfl_xor_sync(0xffffffffu, sendU, 16);
            float V = keepV + __shfl_xor_sync(0xffffffffu, sendV, 16);
            float za, zb;
            gelu2(U + V, U - V, za, zb);       // t0: z(p), z(1024-p); t1: z(512+p), z(512-p)
            // exchange raw z values immediately (starts SHFL earlier in the chain;
            // algebraically identical to shuffling sP/sM)
            float zaO = __shfl_xor_sync(0xffffffffu, za, 16);
            float zbO = __shfl_xor_sync(0xffffffffu, zb, 16);
            float sP = za + zb,   oP = zaO + zbO;   // pair-sums (cos side)
            float sM = zb - za,   oM = zbO - zaO;   // pair-diffs (sin side)
            u64 r2 = pk2(sP + oP, sgn * (sP - oP));
            u64 i2 = pk2(sM + oM, sgn * (sM - oM));
            // fresh table loads for the analysis phase: c2/s2 die at the synth,
            // so ptxas can overlap the next iteration with this one's gelu chain
            u64 c3[8], s3[8];
            lds2u64(c3[0], c3[1], smC_a + off);
            lds2u64(c3[2], c3[3], smC_a + off + 16);
            lds2u64(c3[4], c3[5], smC_a + off + 32);
            lds2u64(c3[6], c3[7], smC_a + off + 48);
            lds2u64(s3[0], s3[1], smS_a + off);
            lds2u64(s3[2], s3[3], smS_a + off + 16);
            lds2u64(s3[4], s3[5], smS_a + off + 32);
            lds2u64(s3[6], s3[7], smS_a + off + 48);
            #pragma unroll
            for (int k = 0; k < 8; k++) {
                zfr2[k] = f2fma(r2, c3[k], zfr2[k]);
                zfi2[k] = f2fma(i2, s3[k], zfi2[k]);
            }
        }
    }

    #pragma unroll
    for (int k = 0; k < 8; k++) {
        float r0, r1, i0, i1;
        un2(zfr2[k], r0, r1);
        un2(zfi2[k], i0, i1);
        int m0 = hh * 16 + 2 * k;
        g_Zf[((size_t)((m0    ) * 2 + 0) * NB + b) * HID + ch] = r0;
        g_Zf[((size_t)((m0    ) * 2 + 1) * NB + b) * HID + ch] = i0;
        g_Zf[((size_t)((m0 + 1) * 2 + 0) * NB + b) * HID + ch] = r1;
        g_Zf[((size_t)((m0 + 1) * 2 + 1) * NB + b) * HID + ch] = i1;
    }
}

// ---------------- K_mix: per-mode complex GEMM, packed FFMA2 (conflict-free) ----------
// Thread outputs o = o_g + 16k (strided): weight LDS.64 across 16 lanes = one 128B line.
__global__ __launch_bounds__(256, 2) void k_mix() {
    int m  = blockIdx.x;
    int bt = blockIdx.y;
    __shared__ float Zr[64 * 17], Zi[64 * 17];
    __shared__ __align__(16) u64 Wp[16 * 128];
    __shared__ __align__(16) u64 Wn[16 * 128];
    int t = threadIdx.x;
    int bo_g = t >> 4, o_g = t & 15;
    int b0 = bo_g * 4;

    u64 acc2[4][8];
    #pragma unroll
    for (int x = 0; x < 4; x++)
        #pragma unroll
        for (int y = 0; y < 8; y++) acc2[x][y] = 0ull;

    const float* Zsr = g_Zf + ((size_t)(m * 2 + 0) * NB + bt * 64) * HID;
    const float* Zsi = g_Zf + ((size_t)(m * 2 + 1) * NB + bt * 64) * HID;

    for (int i0 = 0; i0 < HID; i0 += 16) {
        __syncthreads();
        for (int idx = t; idx < 64 * 16; idx += 256) {
            int bb = idx >> 4, ic = idx & 15;
            Zr[bb * 17 + ic] = Zsr[bb * HID + i0 + ic];
            Zi[bb * 17 + ic] = Zsi[bb * HID + i0 + ic];
        }
        for (int idx = t; idx < 16 * 128; idx += 256) {
            int ic = idx >> 7, o = idx & 127;
            size_t src = ((size_t)m * HID + i0 + ic) * HID + o;
            Wp[idx] = g_w2p[src];
            Wn[idx] = g_w2n[src];
        }
        __syncthreads();
        #pragma unroll 4
        for (int ic = 0; ic < 16; ic++) {
            u64 zrr[4], zii[4];
            #pragma unroll
            for (int bb = 0; bb < 4; bb++) {
                float zr = Zr[(b0 + bb) * 17 + ic];
                float zi = Zi[(b0 + bb) * 17 + ic];
                zrr[bb] = pk2(zr, zr);
                zii[bb] = pk2(zi, zi);
            }
            u64 wp[8], wn[8];
            #pragma unroll
            for (int k = 0; k < 8; k++) {
                wp[k] = Wp[ic * 128 + o_g + 16 * k];
                wn[k] = Wn[ic * 128 + o_g + 16 * k];
            }
            #pragma unroll
            for (int bb = 0; bb < 4; bb++)
                #pragma unroll
                for (int k = 0; k < 8; k++) {
                    acc2[bb][k] = f2fma(zrr[bb], wp[k], acc2[bb][k]);
                    acc2[bb][k] = f2fma(zii[bb], wn[k], acc2[bb][k]);
                }
        }
    }
    #pragma unroll
    for (int bb = 0; bb < 4; bb++) {
        size_t rowr = ((size_t)(m * 2 + 0) * NB + bt * 64 + b0 + bb) * HID;
        size_t rowi = ((size_t)(m * 2 + 1) * NB + bt * 64 + b0 + bb) * HID;
        #pragma unroll
        for (int k = 0; k < 8; k++) {
            float re, im;
            un2(acc2[bb][k], re, im);
            int o = o_g + 16 * k;
            g_of2[rowr + o] = re;
            g_of2[rowi + o] = im;
        }
    }
}

// ---------------- K_layer2: synth + gelu + mean (quad symmetry, smem tables, occ 3) ----
__global__ __launch_bounds__(256, 3) void k_layer2(float* __restrict__ out) {
    __shared__ __align__(16) float smC[64 * 32];
    __shared__ __align__(16) float smS[64 * 32];
    int b = blockIdx.x;
    int t = threadIdx.x;
    int lane = t & 31, w = t >> 5, hh = lane >> 4;
    int o = w * 16 + (lane & 15);
    float sgn  = hh ? -1.0f : 1.0f;
    float msgn = -sgn;

    float br[16], bi[16];
    #pragma unroll
    for (int j = 0; j < 16; j++) {
        int m = hh * 16 + j;
        float orr = __ldg(&g_of2[((size_t)(m * 2 + 0) * NB + b) * HID + o]);
        float oii = __ldg(&g_of2[((size_t)(m * 2 + 1) * NB + b) * HID + o]);
        float km = (m == 0) ? (1.0f / SLEN) : (2.0f / SLEN);
        br[j] = km * orr;
        bi[j] = (m == 0) ? 0.0f : -km * oii;
    }

    const float4* tC = reinterpret_cast<const float4*>(g_tabC);
    const float4* tS = reinterpret_cast<const float4*>(g_tabS);
    int base = hh * 4;
    float acc = 0.0f;                          // per-thread partial (own points only)

    {   // s=0 (t0 adds) and s=512 (t1 adds)
        float c0[16], c5[16];
        #pragma unroll
        for (int q = 0; q < 4; q++) {
            float4 a = __ldg(&tC[0 * 8 + base + q]);
            float4 c = __ldg(&tC[512 * 8 + base + q]);
            c0[4*q+0]=a.x; c0[4*q+1]=a.y; c0[4*q+2]=a.z; c0[4*q+3]=a.w;
            c5[4*q+0]=c.x; c5[4*q+1]=c.y; c5[4*q+2]=c.z; c5[4*q+3]=c.w;
        }
        float u0 = 0.0f, u5 = 0.0f;
        #pragma unroll
        for (int j = 0; j < 16; j++) {
            u0 = fmaf(br[j], c0[j], u0);
            u5 = fmaf(br[j], c5[j], u5);
        }
        u0 += __shfl_xor_sync(0xffffffffu, u0, 16);
        u5 += __shfl_xor_sync(0xffffffffu, u5, 16);
        acc += gelu_fast(hh ? u5 : u0);
    }

    {   // s=256 (t0 adds) / s=768 (t1 adds)
        float c[16], sn[16];
        #pragma unroll
        for (int q = 0; q < 4; q++) {
            float4 a = __ldg(&tC[256 * 8 + base + q]);
            float4 s = __ldg(&tS[256 * 8 + base + q]);
            c [4*q+0]=a.x; c [4*q+1]=a.y; c [4*q+2]=a.z; c [4*q+3]=a.w;
            sn[4*q+0]=s.x; sn[4*q+1]=s.y; sn[4*q+2]=s.z; sn[4*q+3]=s.w;
        }
        float u = 0.0f, v = 0.0f;
        #pragma unroll
        for (int j = 0; j < 16; j++) {
            u = fmaf(br[j], c[j], u);
            v = fmaf(bi[j], sn[j], v);
        }
        float ya = u + v, yb = u - v;
        ya += __shfl_xor_sync(0xffffffffu, ya, 16);
        yb += __shfl_xor_sync(0xffffffffu, yb, 16);
        acc += gelu_fast(hh ? yb : ya);
    }

    // pack
    u64 br2[8], bi2[8];
    #pragma unroll
    for (int k = 0; k < 8; k++) {
        br2[k] = pk2(br[2*k], br[2*k+1]);
        bi2[k] = pk2(bi[2*k], bi[2*k+1]);
    }

    unsigned smC_a = s2u(smC) + hh * 64;
    unsigned smS_a = s2u(smS) + hh * 64;

    for (int pb = 0; pb < 256; pb += 64) {
        __syncthreads();
        for (int j = t; j < 512; j += 256) {
            int row = j >> 3, col = j & 7;
            reinterpret_cast<float4*>(smC)[j] = __ldg(&tC[(pb + row) * 8 + col]);
            reinterpret_cast<float4*>(smS)[j] = __ldg(&tS[(pb + row) * 8 + col]);
        }
        __syncthreads();
        int p0 = (pb == 0) ? 1 : pb;
        for (int p = p0; p < pb + 64; p++) {
            unsigned off = (unsigned)(p - pb) * 128;
            u64 c2[8], s2[8];
            lds2u64(c2[0], c2[1], smC_a + off);
            lds2u64(c2[2], c2[3], smC_a + off + 16);
            lds2u64(c2[4], c2[5], smC_a + off + 32);
            lds2u64(c2[6], c2[7], smC_a + off + 48);
            lds2u64(s2[0], s2[1], smS_a + off);
            lds2u64(s2[2], s2[3], smS_a + off + 16);
            lds2u64(s2[4], s2[5], smS_a + off + 32);
            lds2u64(s2[6], s2[7], smS_a + off + 48);

            u64 u2a = 0ull, u2b = 0ull, v2a = 0ull, v2b = 0ull;
            #pragma unroll
            for (int k = 0; k < 4; k++) {
                u2a = f2fma(br2[k],     c2[k],     u2a);
                u2b = f2fma(br2[k + 4], c2[k + 4], u2b);
                v2a = f2fma(bi2[k],     s2[k],     v2a);
                v2b = f2fma(bi2[k + 4], s2[k + 4], v2b);
            }
            float ue, uo, ve, vo;
            un2(f2add(u2a, u2b), ue, uo);
            un2(f2add(v2a, v2b), ve, vo);
            float keepU = fmaf(sgn,  uo, ue);
            float sendU = fmaf(msgn, uo, ue);
            float keepV = fmaf(sgn,  vo, ve);
            float sendV = fmaf(msgn, vo, ve);
            float U = keepU + __shfl_xor_sync(0xffffffffu, sendU, 16);
            float V = keepV + __shfl_xor_sync(0xffffffffu, sendV, 16);
            float za, zb;
            gelu2(U + V, U - V, za, zb);
            acc += za + zb;
        }
    }

    acc += __shfl_xor_sync(0xffffffffu, acc, 16);
    if (hh == 0) out[(size_t)b * HID + o] = acc * (1.0f / SLEN);
}

// ---------------- launch ----------------
extern "C" void kernel_launch(void* const* d_in, const int* in_sizes, int n_in,
                              void* d_out, int out_size) {
    const float* hin = nullptr;
    const float* w1p[2] = {nullptr, nullptr};
    const float* w2p[2] = {nullptr, nullptr};
    int n1 = 0, n2 = 0;
    for (int i = 0; i < n_in; i++) {
        int sz = in_sizes[i];
        const float* p = (const float*)d_in[i];
        if (sz == NB * SLEN) hin = p;
        else if (sz == HID * NM) { if (n1 < 2) w1p[n1++] = p; }
        else if (sz == HID * HID * NM) { if (n2 < 2) w2p[n2++] = p; }
    }
    float* out = (float*)d_out;

    k_tab<<<(SLEN * NM + 255) / 256, 256>>>();
    k_w<<<(NM * HID * HID + 255) / 256, 256>>>(w1p[0], w1p[1], w2p[0], w2p[1]);
    k_layer1<<<NB, 256>>>(hin);
    dim3 g3(NM, 16);
    k_mix<<<g3, 256>>>();
    k_layer2<<<NB, 256>>>(out);
}

// round 15
// speedup vs baseline: 1.6273x; 1.6273x over previous
#include <cuda_runtime.h>
#include <math.h>

#define SLEN 1024
#define NM   32
#define HID  128
#define NB   1024

typedef unsigned long long u64;

// ---------------- scratch (static device memory; no allocation) ----------------
__device__ float g_tabC[SLEN*NM];          // cos(2*pi*m*s/S), [s][m]
__device__ float g_tabS[SLEN*NM];          // sin(2*pi*m*s/S), [s][m]
__device__ float g_w1tr[NM*HID];           // [m][ch]
__device__ float g_w1ti[NM*HID];
__device__ u64   g_w2p[NM*HID*HID];        // [m][i][o] packed (wr, wi)
__device__ u64   g_w2n[NM*HID*HID];        // [m][i][o] packed (-wi, wr)
__device__ float g_Zf [2*NM*NB*HID];       // [(m*2+ri)][b][ch]
__device__ float g_of2[2*NM*NB*HID];       // [(m*2+ri)][b][o]

// ---------------- packed f32x2 helpers ----------------
__device__ __forceinline__ u64 pk2(float lo, float hi) {
    u64 r; asm("mov.b64 %0, {%1, %2};" : "=l"(r) : "f"(lo), "f"(hi)); return r;
}
__device__ __forceinline__ void un2(u64 v, float& lo, float& hi) {
    asm("mov.b64 {%0, %1}, %2;" : "=f"(lo), "=f"(hi) : "l"(v));
}
__device__ __forceinline__ u64 f2fma(u64 a, u64 b, u64 c) {
    u64 d; asm("fma.rn.f32x2 %0, %1, %2, %3;" : "=l"(d) : "l"(a), "l"(b), "l"(c)); return d;
}
__device__ __forceinline__ u64 f2mul(u64 a, u64 b) {
    u64 d; asm("mul.rn.f32x2 %0, %1, %2;" : "=l"(d) : "l"(a), "l"(b)); return d;
}
__device__ __forceinline__ u64 f2add(u64 a, u64 b) {
    u64 d; asm("add.rn.f32x2 %0, %1, %2;" : "=l"(d) : "l"(a), "l"(b)); return d;
}
__device__ __forceinline__ unsigned s2u(const void* p) {
    return (unsigned)__cvta_generic_to_shared(p);
}
// 16B shared load -> two packed f32x2 operands
__device__ __forceinline__ void lds2u64(u64& a, u64& b, unsigned addr) {
    asm volatile("ld.shared.v2.u64 {%0, %1}, [%2];" : "=l"(a), "=l"(b) : "r"(addr));
}
#define PKC(x) pk2((x), (x))

// High-accuracy GELU (A&S 7.1.26 erf), used on special points only.
__device__ __forceinline__ float gelu_fast(float x) {
    float q    = fabsf(x) * 0.70710678118654752f;
    float t    = __fdividef(1.0f, fmaf(0.3275911f, q, 1.0f));
    float poly = fmaf(fmaf(fmaf(fmaf(1.061405429f, t, -1.453152027f),
                               t, 1.421413741f),
                          t, -0.284496736f),
                      t, 0.254829592f) * t;
    float er   = 1.0f - poly * __expf(-q * q);
    float phi  = fmaf(copysignf(er, x), 0.5f, 0.5f);
    return x * phi;
}

// Two-point GELU, hot path: A&S 7.1.25 3-term erf (abs err 2.5e-5), packed poly.
__device__ __forceinline__ void gelu2(float xa, float xb, float& za, float& zb) {
    float qa = fabsf(xa) * 0.70710678118654752f;
    float qb = fabsf(xb) * 0.70710678118654752f;
    float ta = __fdividef(1.0f, fmaf(0.47047f, qa, 1.0f));
    float tb = __fdividef(1.0f, fmaf(0.47047f, qb, 1.0f));
    u64 t2 = pk2(ta, tb);
    u64 p  = f2fma(t2, PKC(0.7478556f), PKC(-0.0958798f));
    p = f2fma(p, t2, PKC(0.3480242f));
    p = f2mul(p, t2);
    float ea = __expf(-qa * qa), eb = __expf(-qb * qb);
    float pa, pb; un2(p, pa, pb);
    float era = fmaf(-pa, ea, 1.0f), erb = fmaf(-pb, eb, 1.0f);
    za = xa * fmaf(copysignf(era, xa), 0.5f, 0.5f);
    zb = xb * fmaf(copysignf(erb, xb), 0.5f, 0.5f);
}

// ---------------- K_tab: exact trig tables ----------------
__global__ void k_tab() {
    int idx = blockIdx.x * blockDim.x + threadIdx.x;
    if (idx >= SLEN * NM) return;
    int s = idx >> 5, m = idx & 31;
    int k = (s * m) & (SLEN - 1);
    float x = (float)k * (1.0f / 512.0f);
    float sv, cv;
    sincospif(x, &sv, &cv);
    g_tabC[idx] = cv;
    g_tabS[idx] = sv;
}

// ---------------- K_w: weight transposes + complex packing ----------------
__global__ void k_w(const float* __restrict__ w1r, const float* __restrict__ w1i,
                    const float* __restrict__ w2r, const float* __restrict__ w2i) {
    int tid = blockIdx.x * blockDim.x + threadIdx.x;
    if (tid < NM * HID) {
        int ch = tid >> 5, m = tid & 31;
        g_w1tr[m * HID + ch] = w1r[tid];
        g_w1ti[m * HID + ch] = w1i[tid];
    }
    if (tid < NM * HID * HID) {
        int m = tid & 31; int io = tid >> 5;
        int i = io >> 7;  int o = io & 127;
        float wr = w2r[tid], wi = w2i[tid];
        size_t dst = ((size_t)m * HID + i) * HID + o;
        g_w2p[dst] = pk2(wr, wi);
        g_w2n[dst] = pk2(-wi, wr);
    }
}

// ---------------- K_layer1: DFT(h) -> mix w1 -> synth+gelu+analyze (smem tables) -------
__global__ __launch_bounds__(256, 2) void k_layer1(const float* __restrict__ hin) {
    __shared__ float h_sm[SLEN];
    __shared__ float red[64 * 4];
    __shared__ float Hf[64];                   // [0:32) real, [32:64) imag
    __shared__ __align__(16) float smC[64 * 32];   // 64-row chunk of cos table
    __shared__ __align__(16) float smS[64 * 32];   // 64-row chunk of sin table
    int b = blockIdx.x;
    int t = threadIdx.x;

    // stage h row
    {
        const float4* src = reinterpret_cast<const float4*>(hin + (size_t)b * SLEN);
        float4* dst = reinterpret_cast<float4*>(h_sm);
        for (int j = t; j < SLEN / 4; j += 256) dst[j] = src[j];
    }
    __syncthreads();

    // forward DFT of h: Hfr[m] = sum h*cos, Hfi[m] = -sum h*sin
    {
        int out = t & 63, seg = t >> 6;
        int m = out & 31; int isI = out >> 5;
        const float* tab = isI ? g_tabS : g_tabC;
        float acc = 0.0f;
        int s0 = seg * 256;
        #pragma unroll 8
        for (int j = 0; j < 256; j++) {
            int s = s0 + j;
            acc = fmaf(h_sm[s], __ldg(&tab[s * NM + m]), acc);
        }
        red[out * 4 + seg] = acc;
    }
    __syncthreads();
    if (t < 64) {
        float v = red[t * 4] + red[t * 4 + 1] + red[t * 4 + 2] + red[t * 4 + 3];
        Hf[t] = (t >= 32) ? -v : v;
    }
    __syncthreads();

    int lane = t & 31;
    int w    = t >> 5;
    int hh   = lane >> 4;                      // mode-half / point-group owner
    int ch   = w * 16 + (lane & 15);
    float sgn  = hh ? -1.0f : 1.0f;
    float msgn = -sgn;

    // synthesis coefficients: y(s) = sum ar[m]*cos + ai[m]*sin
    float ar[16], ai[16], zfr[16], zfi[16];
    #pragma unroll
    for (int j = 0; j < 16; j++) {
        int m = hh * 16 + j;
        float hr = Hf[m], hi = Hf[32 + m];
        float a1 = __ldg(&g_w1tr[m * HID + ch]);
        float b1 = __ldg(&g_w1ti[m * HID + ch]);
        float km = (m == 0) ? (1.0f / SLEN) : (2.0f / SLEN);
        ar[j] = km * (hr * a1 - hi * b1);
        float oi = km * (hr * b1 + hi * a1);
        ai[j] = (m == 0) ? 0.0f : -oi;         // DC imag dropped by irfft
        zfr[j] = 0.0f; zfi[j] = 0.0f;
    }

    const float4* tC = reinterpret_cast<const float4*>(g_tabC);
    const float4* tS = reinterpret_cast<const float4*>(g_tabS);
    int base = hh * 4;                         // float4 offset inside 8-float4 row

    // special points s=0 and s=512 (sin == 0 there)
    {
        float c0[16], c5[16];
        #pragma unroll
        for (int q = 0; q < 4; q++) {
            float4 a = __ldg(&tC[0 * 8 + base + q]);
            float4 c = __ldg(&tC[512 * 8 + base + q]);
            c0[4*q+0]=a.x; c0[4*q+1]=a.y; c0[4*q+2]=a.z; c0[4*q+3]=a.w;
            c5[4*q+0]=c.x; c5[4*q+1]=c.y; c5[4*q+2]=c.z; c5[4*q+3]=c.w;
        }
        float u0 = 0.0f, u5 = 0.0f;
        #pragma unroll
        for (int j = 0; j < 16; j++) {
            u0 = fmaf(ar[j], c0[j], u0);
            u5 = fmaf(ar[j], c5[j], u5);
        }
        u0 += __shfl_xor_sync(0xffffffffu, u0, 16);
        u5 += __shfl_xor_sync(0xffffffffu, u5, 16);
        float z0 = gelu_fast(u0), z5 = gelu_fast(u5);
        #pragma unroll
        for (int j = 0; j < 16; j++)
            zfr[j] = fmaf(z0, c0[j], fmaf(z5, c5[j], zfr[j]));
    }

    // special pair s=256 / s=768 (half-wave symmetry)
    {
        float c[16], sn[16];
        #pragma unroll
        for (int q = 0; q < 4; q++) {
            float4 a = __ldg(&tC[256 * 8 + base + q]);
            float4 s = __ldg(&tS[256 * 8 + base + q]);
            c [4*q+0]=a.x; c [4*q+1]=a.y; c [4*q+2]=a.z; c [4*q+3]=a.w;
            sn[4*q+0]=s.x; sn[4*q+1]=s.y; sn[4*q+2]=s.z; sn[4*q+3]=s.w;
        }
        float u = 0.0f, v = 0.0f;
        #pragma unroll
        for (int j = 0; j < 16; j++) {
            u = fmaf(ar[j], c[j], u);
            v = fmaf(ai[j], sn[j], v);
        }
        float ya = u + v, yb = u - v;          // y(256), y(768)
        ya += __shfl_xor_sync(0xffffffffu, ya, 16);
        yb += __shfl_xor_sync(0xffffffffu, yb, 16);
        float ymine = hh ? yb : ya;
        float zmine = gelu_fast(ymine);
        float zoth  = __shfl_xor_sync(0xffffffffu, zmine, 16);
        float z0 = hh ? zoth : zmine;          // z(256)
        float z1 = hh ? zmine : zoth;          // z(768)
        float zp = z0 + z1, zd = z1 - z0;
        #pragma unroll
        for (int j = 0; j < 16; j++) {
            zfr[j] = fmaf(zp, c[j],  zfr[j]);
            zfi[j] = fmaf(zd, sn[j], zfi[j]);
        }
    }

    // pack coefficients and accumulators into f32x2 pairs (even/odd mode lanes)
    u64 ar2[8], ai2[8], zfr2[8], zfi2[8];
    #pragma unroll
    for (int k = 0; k < 8; k++) {
        ar2[k]  = pk2(ar[2*k],  ar[2*k+1]);
        ai2[k]  = pk2(ai[2*k],  ai[2*k+1]);
        zfr2[k] = pk2(zfr[2*k], zfr[2*k+1]);
        zfi2[k] = pk2(zfi[2*k], zfi[2*k+1]);
    }

    unsigned smC_a = s2u(smC) + hh * 64;       // hh selects 16-float half of row
    unsigned smS_a = s2u(smS) + hh * 64;

    // quad points {p, 1024-p, 512+p, 512-p}, p = 1..255, smem-staged tables
    for (int pb = 0; pb < 256; pb += 64) {
        __syncthreads();
        // cooperative stage: rows pb..pb+63 of both tables (512 float4 each)
        for (int j = t; j < 512; j += 256) {
            int row = j >> 3, col = j & 7;
            reinterpret_cast<float4*>(smC)[j] = __ldg(&tC[(pb + row) * 8 + col]);
            reinterpret_cast<float4*>(smS)[j] = __ldg(&tS[(pb + row) * 8 + col]);
        }
        __syncthreads();
        int p0 = (pb == 0) ? 1 : pb;
        for (int p = p0; p < pb + 64; p++) {
            unsigned off = (unsigned)(p - pb) * 128;   // 32 floats/row
            u64 c2[8], s2[8];
            lds2u64(c2[0], c2[1], smC_a + off);
            lds2u64(c2[2], c2[3], smC_a + off + 16);
            lds2u64(c2[4], c2[5], smC_a + off + 32);
            lds2u64(c2[6], c2[7], smC_a + off + 48);
            lds2u64(s2[0], s2[1], smS_a + off);
            lds2u64(s2[2], s2[3], smS_a + off + 16);
            lds2u64(s2[4], s2[5], smS_a + off + 32);
            lds2u64(s2[6], s2[7], smS_a + off + 48);

            // split accumulation chains (2x4 deep) for latency
            u64 u2a = 0ull, u2b = 0ull, v2a = 0ull, v2b = 0ull;
            #pragma unroll
            for (int k = 0; k < 4; k++) {
                u2a = f2fma(ar2[k],     c2[k],     u2a);
                u2b = f2fma(ar2[k + 4], c2[k + 4], u2b);
                v2a = f2fma(ai2[k],     s2[k],     v2a);
                v2b = f2fma(ai2[k + 4], s2[k + 4], v2b);
            }
            float ue, uo, ve, vo;
            un2(f2add(u2a, u2b), ue, uo);
            un2(f2add(v2a, v2b), ve, vo);
            // select-free parity folds: keep = my points' combo, send = partner's
            float keepU = fmaf(sgn,  uo, ue);
            float sendU = fmaf(msgn, uo, ue);
            float keepV = fmaf(sgn,  vo, ve);
            float sendV = fmaf(msgn, vo, ve);
            float U = keepU + __shfl_xor_sync(0xffffffffu, sendU, 16);
            float V = keepV + __shfl_xor_sync(0xffffffffu, sendV, 16);
            float za, zb;
            gelu2(U + V, U - V, za, zb);       // t0: z(p), z(1024-p); t1: z(512+p), z(512-p)
            float sP = za + zb;                // pair-sum (cos side)
            float sM = zb - za;                // pair-diff (sin side)
            float oP = __shfl_xor_sync(0xffffffffu, sP, 16);
            float oM = __shfl_xor_sync(0xffffffffu, sM, 16);
            // cos weights: even = sP+oP, odd = sgn*(sP-oP); sin likewise
            u64 r2 = pk2(sP + oP, sgn * (sP - oP));
            u64 i2 = pk2(sM + oM, sgn * (sM - oM));
            #pragma unroll
            for (int k = 0; k < 8; k++) {
                zfr2[k] = f2fma(r2, c2[k], zfr2[k]);
                zfi2[k] = f2fma(i2, s2[k], zfi2[k]);
            }
        }
    }

    #pragma unroll
    for (int k = 0; k < 8; k++) {
        float r0, r1, i0, i1;
        un2(zfr2[k], r0, r1);
        un2(zfi2[k], i0, i1);
        int m0 = hh * 16 + 2 * k;
        g_Zf[((size_t)((m0    ) * 2 + 0) * NB + b) * HID + ch] = r0;
        g_Zf[((size_t)((m0    ) * 2 + 1) * NB + b) * HID + ch] = i0;
        g_Zf[((size_t)((m0 + 1) * 2 + 0) * NB + b) * HID + ch] = r1;
        g_Zf[((size_t)((m0 + 1) * 2 + 1) * NB + b) * HID + ch] = i1;
    }
}

// ---------------- K_mix: per-mode complex GEMM, packed FFMA2 (conflict-free) ----------
// Thread outputs o = o_g + 16k (strided): weight LDS.64 across 16 lanes = one 128B line.
__global__ __launch_bounds__(256, 2) void k_mix() {
    int m  = blockIdx.x;
    int bt = blockIdx.y;
    __shared__ float Zr[64 * 17], Zi[64 * 17];
    __shared__ __align__(16) u64 Wp[16 * 128];
    __shared__ __align__(16) u64 Wn[16 * 128];
    int t = threadIdx.x;
    int bo_g = t >> 4, o_g = t & 15;
    int b0 = bo_g * 4;

    u64 acc2[4][8];
    #pragma unroll
    for (int x = 0; x < 4; x++)
        #pragma unroll
        for (int y = 0; y < 8; y++) acc2[x][y] = 0ull;

    const float* Zsr = g_Zf + ((size_t)(m * 2 + 0) * NB + bt * 64) * HID;
    const float* Zsi = g_Zf + ((size_t)(m * 2 + 1) * NB + bt * 64) * HID;

    for (int i0 = 0; i0 < HID; i0 += 16) {
        __syncthreads();
        for (int idx = t; idx < 64 * 16; idx += 256) {
            int bb = idx >> 4, ic = idx & 15;
            Zr[bb * 17 + ic] = Zsr[bb * HID + i0 + ic];
            Zi[bb * 17 + ic] = Zsi[bb * HID + i0 + ic];
        }
        for (int idx = t; idx < 16 * 128; idx += 256) {
            int ic = idx >> 7, o = idx & 127;
            size_t src = ((size_t)m * HID + i0 + ic) * HID + o;
            Wp[idx] = g_w2p[src];
            Wn[idx] = g_w2n[src];
        }
        __syncthreads();
        #pragma unroll 4
        for (int ic = 0; ic < 16; ic++) {
            u64 zrr[4], zii[4];
            #pragma unroll
            for (int bb = 0; bb < 4; bb++) {
                float zr = Zr[(b0 + bb) * 17 + ic];
                float zi = Zi[(b0 + bb) * 17 + ic];
                zrr[bb] = pk2(zr, zr);
                zii[bb] = pk2(zi, zi);
            }
            u64 wp[8], wn[8];
            #pragma unroll
            for (int k = 0; k < 8; k++) {
                wp[k] = Wp[ic * 128 + o_g + 16 * k];
                wn[k] = Wn[ic * 128 + o_g + 16 * k];
            }
            #pragma unroll
            for (int bb = 0; bb < 4; bb++)
                #pragma unroll
                for (int k = 0; k < 8; k++) {
                    acc2[bb][k] = f2fma(zrr[bb], wp[k], acc2[bb][k]);
                    acc2[bb][k] = f2fma(zii[bb], wn[k], acc2[bb][k]);
                }
        }
    }
    #pragma unroll
    for (int bb = 0; bb < 4; bb++) {
        size_t rowr = ((size_t)(m * 2 + 0) * NB + bt * 64 + b0 + bb) * HID;
        size_t rowi = ((size_t)(m * 2 + 1) * NB + bt * 64 + b0 + bb) * HID;
        #pragma unroll
        for (int k = 0; k < 8; k++) {
            float re, im;
            un2(acc2[bb][k], re, im);
            int o = o_g + 16 * k;
            g_of2[rowr + o] = re;
            g_of2[rowi + o] = im;
        }
    }
}

// ---------------- K_layer2: synth + gelu + mean (quad symmetry, smem tables, occ 3) ----
__global__ __launch_bounds__(256, 3) void k_layer2(float* __restrict__ out) {
    __shared__ __align__(16) float smC[64 * 32];
    __shared__ __align__(16) float smS[64 * 32];
    int b = blockIdx.x;
    int t = threadIdx.x;
    int lane = t & 31, w = t >> 5, hh = lane >> 4;
    int o = w * 16 + (lane & 15);
    float sgn  = hh ? -1.0f : 1.0f;
    float msgn = -sgn;

    float br[16], bi[16];
    #pragma unroll
    for (int j = 0; j < 16; j++) {
        int m = hh * 16 + j;
        float orr = __ldg(&g_of2[((size_t)(m * 2 + 0) * NB + b) * HID + o]);
        float oii = __ldg(&g_of2[((size_t)(m * 2 + 1) * NB + b) * HID + o]);
        float km = (m == 0) ? (1.0f / SLEN) : (2.0f / SLEN);
        br[j] = km * orr;
        bi[j] = (m == 0) ? 0.0f : -km * oii;
    }

    const float4* tC = reinterpret_cast<const float4*>(g_tabC);
    const float4* tS = reinterpret_cast<const float4*>(g_tabS);
    int base = hh * 4;
    float acc = 0.0f;                          // per-thread partial (own points only)

    {   // s=0 (t0 adds) and s=512 (t1 adds)
        float c0[16], c5[16];
        #pragma unroll
        for (int q = 0; q < 4; q++) {
            float4 a = __ldg(&tC[0 * 8 + base + q]);
            float4 c = __ldg(&tC[512 * 8 + base + q]);
            c0[4*q+0]=a.x; c0[4*q+1]=a.y; c0[4*q+2]=a.z; c0[4*q+3]=a.w;
            c5[4*q+0]=c.x; c5[4*q+1]=c.y; c5[4*q+2]=c.z; c5[4*q+3]=c.w;
        }
        float u0 = 0.0f, u5 = 0.0f;
        #pragma unroll
        for (int j = 0; j < 16; j++) {
            u0 = fmaf(br[j], c0[j], u0);
            u5 = fmaf(br[j], c5[j], u5);
        }
        u0 += __shfl_xor_sync(0xffffffffu, u0, 16);
        u5 += __shfl_xor_sync(0xffffffffu, u5, 16);
        acc += gelu_fast(hh ? u5 : u0);
    }

    {   // s=256 (t0 adds) / s=768 (t1 adds)
        float c[16], sn[16];
        #pragma unroll
        for (int q = 0; q < 4; q++) {
            float4 a = __ldg(&tC[256 * 8 + base + q]);
            float4 s = __ldg(&tS[256 * 8 + base + q]);
            c [4*q+0]=a.x; c [4*q+1]=a.y; c [4*q+2]=a.z; c [4*q+3]=a.w;
            sn[4*q+0]=s.x; sn[4*q+1]=s.y; sn[4*q+2]=s.z; sn[4*q+3]=s.w;
        }
        float u = 0.0f, v = 0.0f;
        #pragma unroll
        for (int j = 0; j < 16; j++) {
            u = fmaf(br[j], c[j], u);
            v = fmaf(bi[j], sn[j], v);
        }
        float ya = u + v, yb = u - v;
        ya += __shfl_xor_sync(0xffffffffu, ya, 16);
        yb += __shfl_xor_sync(0xffffffffu, yb, 16);
        acc += gelu_fast(hh ? yb : ya);
    }

    // pack
    u64 br2[8], bi2[8];
    #pragma unroll
    for (int k = 0; k < 8; k++) {
        br2[k] = pk2(br[2*k], br[2*k+1]);
        bi2[k] = pk2(bi[2*k], bi[2*k+1]);
    }

    unsigned smC_a = s2u(smC) + hh * 64;
    unsigned smS_a = s2u(smS) + hh * 64;

    for (int pb = 0; pb < 256; pb += 64) {
        __syncthreads();
        for (int j = t; j < 512; j += 256) {
            int row = j >> 3, col = j & 7;
            reinterpret_cast<float4*>(smC)[j] = __ldg(&tC[(pb + row) * 8 + col]);
            reinterpret_cast<float4*>(smS)[j] = __ldg(&tS[(pb + row) * 8 + col]);
        }
        __syncthreads();
        int p0 = (pb == 0) ? 1 : pb;
        for (int p = p0; p < pb + 64; p++) {
            unsigned off = (unsigned)(p - pb) * 128;
            u64 c2[8], s2[8];
            lds2u64(c2[0], c2[1], smC_a + off);
            lds2u64(c2[2], c2[3], smC_a + off + 16);
            lds2u64(c2[4], c2[5], smC_a + off + 32);
            lds2u64(c2[6], c2[7], smC_a + off + 48);
            lds2u64(s2[0], s2[1], smS_a + off);
            lds2u64(s2[2], s2[3], smS_a + off + 16);
            lds2u64(s2[4], s2[5], smS_a + off + 32);
            lds2u64(s2[6], s2[7], smS_a + off + 48);

            u64 u2a = 0ull, u2b = 0ull, v2a = 0ull, v2b = 0ull;
            #pragma unroll
            for (int k = 0; k < 4; k++) {
                u2a = f2fma(br2[k],     c2[k],     u2a);
                u2b = f2fma(br2[k + 4], c2[k + 4], u2b);
                v2a = f2fma(bi2[k],     s2[k],     v2a);
                v2b = f2fma(bi2[k + 4], s2[k + 4], v2b);
            }
            float ue, uo, ve, vo;
            un2(f2add(u2a, u2b), ue, uo);
            un2(f2add(v2a, v2b), ve, vo);
            float keepU = fmaf(sgn,  uo, ue);
            float sendU = fmaf(msgn, uo, ue);
            float keepV = fmaf(sgn,  vo, ve);
            float sendV = fmaf(msgn, vo, ve);
            float U = keepU + __shfl_xor_sync(0xffffffffu, sendU, 16);
            float V = keepV + __shfl_xor_sync(0xffffffffu, sendV, 16);
            float za, zb;
            gelu2(U + V, U - V, za, zb);
            acc += za + zb;
        }
    }

    acc += __shfl_xor_sync(0xffffffffu, acc, 16);
    if (hh == 0) out[(size_t)b * HID + o] = acc * (1.0f / SLEN);
}

// ---------------- launch ----------------
extern "C" void kernel_launch(void* const* d_in, const int* in_sizes, int n_in,
                              void* d_out, int out_size) {
    const float* hin = nullptr;
    const float* w1p[2] = {nullptr, nullptr};
    const float* w2p[2] = {nullptr, nullptr};
    int n1 = 0, n2 = 0;
    for (int i = 0; i < n_in; i++) {
        int sz = in_sizes[i];
        const float* p = (const float*)d_in[i];
        if (sz == NB * SLEN) hin = p;
        else if (sz == HID * NM) { if (n1 < 2) w1p[n1++] = p; }
        else if (sz == HID * HID * NM) { if (n2 < 2) w2p[n2++] = p; }
    }
    float* out = (float*)d_out;

    k_tab<<<(SLEN * NM + 255) / 256, 256>>>();
    k_w<<<(NM * HID * HID + 255) / 256, 256>>>(w1p[0], w1p[1], w2p[0], w2p[1]);
    k_layer1<<<NB, 256>>>(hin);
    dim3 g3(NM, 16);
    k_mix<<<g3, 256>>>();
    k_layer2<<<NB, 256>>>(out);
}